// round 3
// baseline (speedup 1.0000x reference)
#include <cuda_runtime.h>
#include <cuda_bf16.h>
#include <cstdint>
#include <math.h>

// ============================ Problem constants =============================
#define B_DIM 4096
#define H_DIM 1024
#define K_DIM 2048        // concat K = INPUT + HIDDEN
#define N_DIM 4096        // 4*H, interleaved: n' = 16*(j>>2) + 8*(g>>1) + 2*(j&3) + (g&1)

#define BM 128
#define BN 128
#define BK 64
#define KTILES (K_DIM / BK)   // 32

// ============================ Scratch (static) ==============================
__device__ __nv_bfloat16 g_Ahi[(size_t)B_DIM * K_DIM];
__device__ __nv_bfloat16 g_Alo[(size_t)B_DIM * K_DIM];
__device__ __nv_bfloat16 g_Bhi[(size_t)N_DIM * K_DIM];
__device__ __nv_bfloat16 g_Blo[(size_t)N_DIM * K_DIM];

// ============================ PTX helpers ===================================
__device__ __forceinline__ uint32_t smem_u32(const void* p) {
    uint32_t a;
    asm("{ .reg .u64 t; cvta.to.shared.u64 t, %1; cvt.u32.u64 %0, t; }"
        : "=r"(a) : "l"(p));
    return a;
}

__device__ __forceinline__ void cp16(uint32_t s, const void* g) {
    asm volatile("cp.async.cg.shared.global [%0], [%1], 16;" :: "r"(s), "l"(g));
}
#define CP_COMMIT() asm volatile("cp.async.commit_group;" ::: "memory")
#define CP_WAIT1()  asm volatile("cp.async.wait_group 1;" ::: "memory")
#define CP_WAIT0()  asm volatile("cp.async.wait_group 0;" ::: "memory")

#define LDSM_X4(r, addr)                                                      \
    asm volatile("ldmatrix.sync.aligned.m8n8.x4.shared.b16 {%0,%1,%2,%3}, [%4];" \
        : "=r"((r)[0]), "=r"((r)[1]), "=r"((r)[2]), "=r"((r)[3]) : "r"(addr))

__device__ __forceinline__ void mma_bf16(float* c, const uint32_t* a,
                                         uint32_t b0, uint32_t b1) {
    asm volatile(
        "mma.sync.aligned.m16n8k16.row.col.f32.bf16.bf16.f32 "
        "{%0,%1,%2,%3}, {%4,%5,%6,%7}, {%8,%9}, {%0,%1,%2,%3};"
        : "+f"(c[0]), "+f"(c[1]), "+f"(c[2]), "+f"(c[3])
        : "r"(a[0]), "r"(a[1]), "r"(a[2]), "r"(a[3]), "r"(b0), "r"(b1));
}

// ============================ SMEM layout ===================================
static constexpr int OFF_AHI = 0, OFF_ALO = 16384, OFF_BHI = 32768, OFF_BLO = 49152;
static constexpr int STAGE_SZ  = 65536;
static constexpr int SMEM_BYTES = 2 * STAGE_SZ;     // 128 KB

// ============================ Prep kernels ==================================
__device__ __forceinline__ uint32_t pack2(__nv_bfloat16 a, __nv_bfloat16 b) {
    __nv_bfloat162 t = __halves2bfloat162(a, b);
    return *reinterpret_cast<uint32_t*>(&t);
}

__global__ void prep_A_kernel(const float* __restrict__ x, const float* __restrict__ h) {
    size_t t = (size_t)blockIdx.x * blockDim.x + threadIdx.x;   // 4096*512 threads
    int row = (int)(t >> 9);
    int kq  = ((int)t & 511) << 2;
    const float* src = (kq < 1024) ? (x + (size_t)row * 1024 + kq)
                                   : (h + (size_t)row * 1024 + (kq - 1024));
    float4 v = *reinterpret_cast<const float4*>(src);
    __nv_bfloat16 h0 = __float2bfloat16(v.x), h1 = __float2bfloat16(v.y);
    __nv_bfloat16 h2 = __float2bfloat16(v.z), h3 = __float2bfloat16(v.w);
    __nv_bfloat16 l0 = __float2bfloat16(v.x - __bfloat162float(h0));
    __nv_bfloat16 l1 = __float2bfloat16(v.y - __bfloat162float(h1));
    __nv_bfloat16 l2 = __float2bfloat16(v.z - __bfloat162float(h2));
    __nv_bfloat16 l3 = __float2bfloat16(v.w - __bfloat162float(h3));
    size_t o = (size_t)row * K_DIM + kq;
    *reinterpret_cast<uint2*>(g_Ahi + o) = make_uint2(pack2(h0, h1), pack2(h2, h3));
    *reinterpret_cast<uint2*>(g_Alo + o) = make_uint2(pack2(l0, l1), pack2(l2, l3));
}

// Transpose W/U [K,H] -> B [n', k] (K-major), hi/lo split, SMEM transpose.
// n'(j,g) = 16*(j>>2) + 8*(g>>1) + 2*(j&3) + (g&1)
__global__ void prep_W_kernel(
    const float* __restrict__ Wf, const float* __restrict__ Wi,
    const float* __restrict__ Wc, const float* __restrict__ Wo,
    const float* __restrict__ Uf, const float* __restrict__ Ui,
    const float* __restrict__ Uc, const float* __restrict__ Uo)
{
    __shared__ float s[32][33];
    const int g  = blockIdx.z;
    const int k0 = blockIdx.x * 32;
    const int j0 = blockIdx.y * 32;
    const float* W[4] = {Wf, Wi, Wc, Wo};
    const float* U[4] = {Uf, Ui, Uc, Uo};
    const float* src; int krel;
    if (k0 < 1024) { src = W[g]; krel = k0; } else { src = U[g]; krel = k0 - 1024; }
    const int tx = threadIdx.x, ty = threadIdx.y;     // 32 x 8
    #pragma unroll
    for (int r = 0; r < 32; r += 8)
        s[ty + r][tx] = src[(size_t)(krel + ty + r) * 1024 + j0 + tx];
    __syncthreads();
    #pragma unroll
    for (int r = 0; r < 32; r += 8) {
        const int j = j0 + ty + r;
        const int k = k0 + tx;
        float v = s[tx][ty + r];
        __nv_bfloat16 hi = __float2bfloat16(v);
        __nv_bfloat16 lo = __float2bfloat16(v - __bfloat162float(hi));
        const int np = 16 * (j >> 2) + 8 * (g >> 1) + 2 * (j & 3) + (g & 1);
        size_t o = (size_t)np * K_DIM + k;
        g_Bhi[o] = hi;
        g_Blo[o] = lo;
    }
}

// ============================ GEMM + fused LSTM =============================
__device__ __forceinline__ void load_stage(uint32_t st, int kt, int m0, int n0) {
    const int k0 = kt * BK;
    #pragma unroll
    for (int i = 0; i < 4; i++) {
        int c = threadIdx.x + i * 256;              // 1024 chunk slots (128 rows x 8)
        int row = c >> 3, ch = c & 7;
        uint32_t so = (uint32_t)(row * 128 + ((ch ^ (row & 7)) << 4));
        size_t ga = (size_t)(m0 + row) * K_DIM + k0 + ch * 8;
        size_t gb = (size_t)(n0 + row) * K_DIM + k0 + ch * 8;
        cp16(st + OFF_AHI + so, g_Ahi + ga);
        cp16(st + OFF_ALO + so, g_Alo + ga);
        cp16(st + OFF_BHI + so, g_Bhi + gb);
        cp16(st + OFF_BLO + so, g_Blo + gb);
    }
    CP_COMMIT();
}

__global__ void __launch_bounds__(256, 1) lstm_gemm_kernel(
    const float* __restrict__ c_prev,
    const float* __restrict__ b_f, const float* __restrict__ b_i,
    const float* __restrict__ b_c, const float* __restrict__ b_o,
    float* __restrict__ out)
{
    extern __shared__ __align__(128) char dsmem[];
    const uint32_t sb = smem_u32(dsmem);
    const int tid = threadIdx.x, wid = tid >> 5, l = tid & 31;
    const int warp_m = wid >> 1, warp_n = wid & 1;
    const int m0 = blockIdx.y * BM, n0 = blockIdx.x * BN;

    float acc[2][8][4];
    #pragma unroll
    for (int a = 0; a < 2; a++)
        #pragma unroll
        for (int b = 0; b < 8; b++)
            #pragma unroll
            for (int c = 0; c < 4; c++) acc[a][b][c] = 0.0f;

    // lane-derived ldmatrix addressing
    const uint32_t swx    = l & 7;
    const uint32_t a_row  = warp_m * 32 + (l & 15);
    const uint32_t a_kc   = l >> 4;                       // extra k-chunk bit
    const uint32_t b_row  = warp_n * 64 + (l & 7) + ((l >> 4) << 3);
    const uint32_t b_kc   = (l >> 3) & 1;

    load_stage(sb, 0, m0, n0);
    load_stage(sb + STAGE_SZ, 1, m0, n0);

    for (int kt = 0; kt < KTILES; kt++) {
        if (kt + 2 < KTILES) { CP_WAIT1(); } else { CP_WAIT0(); }
        __syncthreads();
        const uint32_t st = sb + (kt & 1) * STAGE_SZ;

        #pragma unroll
        for (int ks = 0; ks < 4; ks++) {
            uint32_t ahi[2][4], alo[2][4], bhi[4][4], blo[4][4];
            #pragma unroll
            for (int mi = 0; mi < 2; mi++) {
                uint32_t off = (a_row + mi * 16) * 128 + (((ks * 2 + a_kc) ^ swx) << 4);
                LDSM_X4(ahi[mi], st + OFF_AHI + off);
                LDSM_X4(alo[mi], st + OFF_ALO + off);
            }
            #pragma unroll
            for (int nb = 0; nb < 4; nb++) {
                uint32_t off = (b_row + nb * 16) * 128 + (((ks * 2 + b_kc) ^ swx) << 4);
                LDSM_X4(bhi[nb], st + OFF_BHI + off);
                LDSM_X4(blo[nb], st + OFF_BLO + off);
            }
            #pragma unroll
            for (int mi = 0; mi < 2; mi++)
                #pragma unroll
                for (int ni = 0; ni < 8; ni++) {
                    const int nb = ni >> 1, q = (ni & 1) * 2;
                    mma_bf16(acc[mi][ni], ahi[mi], bhi[nb][q], bhi[nb][q + 1]);
                    mma_bf16(acc[mi][ni], ahi[mi], blo[nb][q], blo[nb][q + 1]);
                    mma_bf16(acc[mi][ni], alo[mi], bhi[nb][q], bhi[nb][q + 1]);
                }
        }
        __syncthreads();
        if (kt + 2 < KTILES) load_stage(st, kt + 2, m0, n0);
    }

    // -------- fused LSTM epilogue (fully thread-local) --------
    // thread owns: rows = m0 + warp_m*32 + mi*16 + h*8 + (l>>2)
    //              j    = n0/4 + warp_n*16 + 4p + (l&3)
    const int t  = l & 3, rg = l >> 2;
    const int row0  = m0 + warp_m * 32;
    const int jbase = (n0 >> 2) + warp_n * 16 + t;
    #pragma unroll
    for (int p = 0; p < 4; p++) {
        const int j = jbase + 4 * p;
        const float bf = __ldg(b_f + j), bi = __ldg(b_i + j);
        const float bc = __ldg(b_c + j), bo = __ldg(b_o + j);
        #pragma unroll
        for (int mi = 0; mi < 2; mi++)
            #pragma unroll
            for (int h = 0; h < 2; h++) {
                const int row = row0 + mi * 16 + h * 8 + rg;
                float gf = acc[mi][2 * p][2 * h]     + bf;
                float gi = acc[mi][2 * p][2 * h + 1] + bi;
                float gc = acc[mi][2 * p + 1][2 * h]     + bc;
                float go = acc[mi][2 * p + 1][2 * h + 1] + bo;
                float f  = 1.0f / (1.0f + expf(-gf));
                float ii = 1.0f / (1.0f + expf(-gi));
                float ct = tanhf(gc);
                float oo = 1.0f / (1.0f + expf(-go));
                float cp = __ldg(c_prev + (size_t)row * H_DIM + j);
                float cn = f * cp + ii * ct;
                out[(size_t)row * H_DIM + j] = oo * tanhf(cn);
            }
    }
}

// ============================ Launch ========================================
extern "C" void kernel_launch(void* const* d_in, const int* in_sizes, int n_in,
                              void* d_out, int out_size) {
    const float* x  = (const float*)d_in[0];
    const float* h  = (const float*)d_in[1];
    const float* cp = (const float*)d_in[2];
    const float* Wf = (const float*)d_in[3];
    const float* Wi = (const float*)d_in[4];
    const float* Wc = (const float*)d_in[5];
    const float* Wo = (const float*)d_in[6];
    const float* Uf = (const float*)d_in[7];
    const float* Ui = (const float*)d_in[8];
    const float* Uc = (const float*)d_in[9];
    const float* Uo = (const float*)d_in[10];
    const float* bf = (const float*)d_in[11];
    const float* bi = (const float*)d_in[12];
    const float* bc = (const float*)d_in[13];
    const float* bo = (const float*)d_in[14];
    float* out = (float*)d_out;

    cudaFuncSetAttribute(lstm_gemm_kernel,
                         cudaFuncAttributeMaxDynamicSharedMemorySize, SMEM_BYTES);

    prep_A_kernel<<<8192, 256>>>(x, h);
    prep_W_kernel<<<dim3(64, 32, 4), dim3(32, 8)>>>(Wf, Wi, Wc, Wo, Uf, Ui, Uc, Uo);
    lstm_gemm_kernel<<<dim3(N_DIM / BN, B_DIM / BM), 256, SMEM_BYTES>>>(
        cp, bf, bi, bc, bo, out);
}

// round 4
// speedup vs baseline: 1.0154x; 1.0154x over previous
#include <cuda_runtime.h>
#include <cuda_bf16.h>
#include <cstdint>
#include <math.h>

// ============================ Problem constants =============================
#define B_DIM 4096
#define H_DIM 1024
#define K_DIM 2048        // concat K = INPUT + HIDDEN
#define N_DIM 4096        // 4*H, interleaved: n' = 16*(j>>2) + 8*(g>>1) + 2*(j&3) + (g&1)

#define BM 128
#define BN 128
#define BK 64
#define KTILES (K_DIM / BK)   // 32

// ============================ Scratch (static) ==============================
__device__ __nv_bfloat16 g_Ahi[(size_t)B_DIM * K_DIM];
__device__ __nv_bfloat16 g_Alo[(size_t)B_DIM * K_DIM];
__device__ __nv_bfloat16 g_Bhi[(size_t)N_DIM * K_DIM];
__device__ __nv_bfloat16 g_Blo[(size_t)N_DIM * K_DIM];

// ============================ PTX helpers ===================================
__device__ __forceinline__ uint32_t smem_u32(const void* p) {
    uint32_t a;
    asm("{ .reg .u64 t; cvta.to.shared.u64 t, %1; cvt.u32.u64 %0, t; }"
        : "=r"(a) : "l"(p));
    return a;
}

__device__ __forceinline__ void cp16(uint32_t s, const void* g) {
    asm volatile("cp.async.cg.shared.global [%0], [%1], 16;" :: "r"(s), "l"(g));
}
#define CP_COMMIT() asm volatile("cp.async.commit_group;" ::: "memory")
#define CP_WAIT1()  asm volatile("cp.async.wait_group 1;" ::: "memory")
#define CP_WAIT0()  asm volatile("cp.async.wait_group 0;" ::: "memory")

#define LDSM_X4(r, addr)                                                      \
    asm volatile("ldmatrix.sync.aligned.m8n8.x4.shared.b16 {%0,%1,%2,%3}, [%4];" \
        : "=r"((r)[0]), "=r"((r)[1]), "=r"((r)[2]), "=r"((r)[3]) : "r"(addr))

__device__ __forceinline__ void mma_bf16(float* c, const uint32_t* a,
                                         uint32_t b0, uint32_t b1) {
    asm volatile(
        "mma.sync.aligned.m16n8k16.row.col.f32.bf16.bf16.f32 "
        "{%0,%1,%2,%3}, {%4,%5,%6,%7}, {%8,%9}, {%0,%1,%2,%3};"
        : "+f"(c[0]), "+f"(c[1]), "+f"(c[2]), "+f"(c[3])
        : "r"(a[0]), "r"(a[1]), "r"(a[2]), "r"(a[3]), "r"(b0), "r"(b1));
}

// ============================ SMEM layout ===================================
static constexpr int OFF_AHI = 0, OFF_ALO = 16384, OFF_BHI = 32768, OFF_BLO = 49152;
static constexpr int STAGE_SZ  = 65536;
static constexpr int NSTAGES   = 3;
static constexpr int SMEM_BYTES = NSTAGES * STAGE_SZ;     // 192 KB

// ============================ Prep kernels ==================================
__device__ __forceinline__ uint32_t pack2(__nv_bfloat16 a, __nv_bfloat16 b) {
    __nv_bfloat162 t = __halves2bfloat162(a, b);
    return *reinterpret_cast<uint32_t*>(&t);
}

__global__ void prep_A_kernel(const float* __restrict__ x, const float* __restrict__ h) {
    size_t t = (size_t)blockIdx.x * blockDim.x + threadIdx.x;   // 4096*512 threads
    int row = (int)(t >> 9);
    int kq  = ((int)t & 511) << 2;
    const float* src = (kq < 1024) ? (x + (size_t)row * 1024 + kq)
                                   : (h + (size_t)row * 1024 + (kq - 1024));
    float4 v = *reinterpret_cast<const float4*>(src);
    __nv_bfloat16 h0 = __float2bfloat16(v.x), h1 = __float2bfloat16(v.y);
    __nv_bfloat16 h2 = __float2bfloat16(v.z), h3 = __float2bfloat16(v.w);
    __nv_bfloat16 l0 = __float2bfloat16(v.x - __bfloat162float(h0));
    __nv_bfloat16 l1 = __float2bfloat16(v.y - __bfloat162float(h1));
    __nv_bfloat16 l2 = __float2bfloat16(v.z - __bfloat162float(h2));
    __nv_bfloat16 l3 = __float2bfloat16(v.w - __bfloat162float(h3));
    size_t o = (size_t)row * K_DIM + kq;
    *reinterpret_cast<uint2*>(g_Ahi + o) = make_uint2(pack2(h0, h1), pack2(h2, h3));
    *reinterpret_cast<uint2*>(g_Alo + o) = make_uint2(pack2(l0, l1), pack2(l2, l3));
}

// Transpose W/U [K,H] -> B [n', k] (K-major), hi/lo split, SMEM transpose.
// n'(j,g) = 16*(j>>2) + 8*(g>>1) + 2*(j&3) + (g&1)
// Vectorized: each thread writes 4 consecutive k (8-byte stores).
__global__ void prep_W_kernel(
    const float* __restrict__ Wf, const float* __restrict__ Wi,
    const float* __restrict__ Wc, const float* __restrict__ Wo,
    const float* __restrict__ Uf, const float* __restrict__ Ui,
    const float* __restrict__ Uc, const float* __restrict__ Uo)
{
    __shared__ float s[32][33];
    const int g  = blockIdx.z;
    const int k0 = blockIdx.x * 32;
    const int j0 = blockIdx.y * 32;
    const float* W[4] = {Wf, Wi, Wc, Wo};
    const float* U[4] = {Uf, Ui, Uc, Uo};
    const float* src; int krel;
    if (k0 < 1024) { src = W[g]; krel = k0; } else { src = U[g]; krel = k0 - 1024; }
    const int tid = threadIdx.x;                 // 256 threads
    const int tx = tid & 31, ty = tid >> 5;      // 32 x 8 for the load
    #pragma unroll
    for (int r = 0; r < 32; r += 8)
        s[ty + r][tx] = src[(size_t)(krel + ty + r) * 1024 + j0 + tx];
    __syncthreads();
    // write: jj = tid>>3 (0..31), kc = tid&7 (0..7) -> 4 consecutive k each
    const int jj = tid >> 3, kc = tid & 7;
    const int j  = j0 + jj;
    const int np = 16 * (j >> 2) + 8 * (g >> 1) + 2 * (j & 3) + (g & 1);
    __nv_bfloat16 hi[4], lo[4];
    #pragma unroll
    for (int q = 0; q < 4; q++) {
        float v = s[kc * 4 + q][jj];
        hi[q] = __float2bfloat16(v);
        lo[q] = __float2bfloat16(v - __bfloat162float(hi[q]));
    }
    size_t o = (size_t)np * K_DIM + k0 + kc * 4;
    *reinterpret_cast<uint2*>(g_Bhi + o) = make_uint2(pack2(hi[0], hi[1]), pack2(hi[2], hi[3]));
    *reinterpret_cast<uint2*>(g_Blo + o) = make_uint2(pack2(lo[0], lo[1]), pack2(lo[2], lo[3]));
}

// ============================ GEMM + fused LSTM =============================
__device__ __forceinline__ void load_stage(uint32_t st, int kt, int m0, int n0) {
    const int k0 = kt * BK;
    #pragma unroll
    for (int i = 0; i < 4; i++) {
        int c = threadIdx.x + i * 256;              // 1024 chunk slots (128 rows x 8)
        int row = c >> 3, ch = c & 7;
        uint32_t so = (uint32_t)(row * 128 + ((ch ^ (row & 7)) << 4));
        size_t ga = (size_t)(m0 + row) * K_DIM + k0 + ch * 8;
        size_t gb = (size_t)(n0 + row) * K_DIM + k0 + ch * 8;
        cp16(st + OFF_AHI + so, g_Ahi + ga);
        cp16(st + OFF_ALO + so, g_Alo + ga);
        cp16(st + OFF_BHI + so, g_Bhi + gb);
        cp16(st + OFF_BLO + so, g_Blo + gb);
    }
    CP_COMMIT();
}

__global__ void __launch_bounds__(256, 1) lstm_gemm_kernel(
    const float* __restrict__ c_prev,
    const float* __restrict__ b_f, const float* __restrict__ b_i,
    const float* __restrict__ b_c, const float* __restrict__ b_o,
    float* __restrict__ out)
{
    extern __shared__ __align__(128) char dsmem[];
    const uint32_t sb = smem_u32(dsmem);
    const int tid = threadIdx.x, wid = tid >> 5, l = tid & 31;
    const int warp_m = wid >> 1, warp_n = wid & 1;
    const int m0 = blockIdx.y * BM, n0 = blockIdx.x * BN;

    float acc[2][8][4];
    #pragma unroll
    for (int a = 0; a < 2; a++)
        #pragma unroll
        for (int b = 0; b < 8; b++)
            #pragma unroll
            for (int c = 0; c < 4; c++) acc[a][b][c] = 0.0f;

    // lane-derived ldmatrix addressing
    const uint32_t swx    = l & 7;
    const uint32_t a_row  = warp_m * 32 + (l & 15);
    const uint32_t a_kc   = l >> 4;                       // extra k-chunk bit
    const uint32_t b_row  = warp_n * 64 + (l & 7) + ((l >> 4) << 3);
    const uint32_t b_kc   = (l >> 3) & 1;

    // 3-stage ring: p0 = compute stage, p1 = next, p2 = fill target
    uint32_t p0 = sb, p1 = sb + STAGE_SZ, p2 = sb + 2 * STAGE_SZ;

    load_stage(p0, 0, m0, n0);
    load_stage(p1, 1, m0, n0);

    for (int kt = 0; kt < KTILES; kt++) {
        if (kt + 2 < KTILES) { CP_WAIT1(); } else { CP_WAIT0(); }
        __syncthreads();
        if (kt + 2 < KTILES) load_stage(p2, kt + 2, m0, n0);
        const uint32_t st = p0;

        #pragma unroll
        for (int ks = 0; ks < 4; ks++) {
            uint32_t ahi[2][4], alo[2][4], bhi[4][4], blo[4][4];
            #pragma unroll
            for (int mi = 0; mi < 2; mi++) {
                uint32_t off = (a_row + mi * 16) * 128 + (((ks * 2 + a_kc) ^ swx) << 4);
                LDSM_X4(ahi[mi], st + OFF_AHI + off);
                LDSM_X4(alo[mi], st + OFF_ALO + off);
            }
            #pragma unroll
            for (int nb = 0; nb < 4; nb++) {
                uint32_t off = (b_row + nb * 16) * 128 + (((ks * 2 + b_kc) ^ swx) << 4);
                LDSM_X4(bhi[nb], st + OFF_BHI + off);
                LDSM_X4(blo[nb], st + OFF_BLO + off);
            }
            #pragma unroll
            for (int mi = 0; mi < 2; mi++)
                #pragma unroll
                for (int ni = 0; ni < 8; ni++) {
                    const int nb = ni >> 1, q = (ni & 1) * 2;
                    mma_bf16(acc[mi][ni], ahi[mi], bhi[nb][q], bhi[nb][q + 1]);
                    mma_bf16(acc[mi][ni], ahi[mi], blo[nb][q], blo[nb][q + 1]);
                    mma_bf16(acc[mi][ni], alo[mi], bhi[nb][q], bhi[nb][q + 1]);
                }
        }
        // rotate ring
        uint32_t t0 = p0; p0 = p1; p1 = p2; p2 = t0;
    }

    // -------- fused LSTM epilogue (fully thread-local) --------
    // thread owns: rows = m0 + warp_m*32 + mi*16 + h*8 + (l>>2)
    //              j    = n0/4 + warp_n*16 + 4p + (l&3)
    const int t  = l & 3, rg = l >> 2;
    const int row0  = m0 + warp_m * 32;
    const int jbase = (n0 >> 2) + warp_n * 16 + t;
    #pragma unroll
    for (int p = 0; p < 4; p++) {
        const int j = jbase + 4 * p;
        const float bf = __ldg(b_f + j), bi = __ldg(b_i + j);
        const float bc = __ldg(b_c + j), bo = __ldg(b_o + j);
        #pragma unroll
        for (int mi = 0; mi < 2; mi++)
            #pragma unroll
            for (int h = 0; h < 2; h++) {
                const int row = row0 + mi * 16 + h * 8 + rg;
                float gf = acc[mi][2 * p][2 * h]     + bf;
                float gi = acc[mi][2 * p][2 * h + 1] + bi;
                float gc = acc[mi][2 * p + 1][2 * h]     + bc;
                float go = acc[mi][2 * p + 1][2 * h + 1] + bo;
                float f  = 1.0f / (1.0f + expf(-gf));
                float ii = 1.0f / (1.0f + expf(-gi));
                float ct = tanhf(gc);
                float oo = 1.0f / (1.0f + expf(-go));
                float cp = __ldg(c_prev + (size_t)row * H_DIM + j);
                float cn = f * cp + ii * ct;
                out[(size_t)row * H_DIM + j] = oo * tanhf(cn);
            }
    }
}

// ============================ Launch ========================================
extern "C" void kernel_launch(void* const* d_in, const int* in_sizes, int n_in,
                              void* d_out, int out_size) {
    const float* x  = (const float*)d_in[0];
    const float* h  = (const float*)d_in[1];
    const float* cp = (const float*)d_in[2];
    const float* Wf = (const float*)d_in[3];
    const float* Wi = (const float*)d_in[4];
    const float* Wc = (const float*)d_in[5];
    const float* Wo = (const float*)d_in[6];
    const float* Uf = (const float*)d_in[7];
    const float* Ui = (const float*)d_in[8];
    const float* Uc = (const float*)d_in[9];
    const float* Uo = (const float*)d_in[10];
    const float* bf = (const float*)d_in[11];
    const float* bi = (const float*)d_in[12];
    const float* bc = (const float*)d_in[13];
    const float* bo = (const float*)d_in[14];
    float* out = (float*)d_out;

    cudaFuncSetAttribute(lstm_gemm_kernel,
                         cudaFuncAttributeMaxDynamicSharedMemorySize, SMEM_BYTES);

    prep_A_kernel<<<8192, 256>>>(x, h);
    prep_W_kernel<<<dim3(64, 32, 4), dim3(32 * 8)>>>(Wf, Wi, Wc, Wo, Uf, Ui, Uc, Uo);
    lstm_gemm_kernel<<<dim3(N_DIM / BN, B_DIM / BM), 256, SMEM_BYTES>>>(
        cp, bf, bi, bc, bo, out);
}